// round 13
// baseline (speedup 1.0000x reference)
#include <cuda_runtime.h>

// HolographicLayer: eta = dot(R[p], ccorr_half(E[s], E[o]))
//   ccorr_half(a,b)[k] = sum_i a[k+i-100] * b[i], zero-padded, d=201
// With padded smem sp (sp[100+j] = a[j], zeros elsewhere):
//   eta = sum_k rv[k] * sum_i sp[k+i] * bv[i]
// Single block, 256 threads. Thread t owns a 4-k x 44-i register tile:
//   tc = t/51 (i-chunk), tk = t%51 (k-group of 4).
// Sliding-window sp loads (one new float4 per iteration), scalar FFMA
// with 4 independent accumulators (best-measured variant: beat both the
// f32x2-packed and redux experiments). x read as one int4 LDG to shorten
// the head of the dependent load chain.

#define D      201
#define PAD    100
#define NT     256
#define SPLEN  480    // max sp index touched: 200+220+47 = 467
#define BVLEN  264    // max bv index touched: 220+43    = 263

__global__ void __launch_bounds__(NT, 1)
holo_kernel(const int* __restrict__ x,
            const float* __restrict__ E,
            const float* __restrict__ R,
            float* __restrict__ out) {
    __shared__ __align__(16) float sp[SPLEN];
    __shared__ __align__(16) float bv[BVLEN];
    __shared__ __align__(16) float wsum[NT / 32];

    const int t = threadIdx.x;

    // x is [32,3] row-major; row 0 = (s, o, p). One 16B load grabs all
    // three indices (harness buffers are 16B-aligned; x[3] is don't-care).
    const int4 xi = *reinterpret_cast<const int4*>(x);
    const int s = xi.x, o = xi.y, p = xi.z;
    const float* __restrict__ Es = E + (long long)s * D;
    const float* __restrict__ Eo = E + (long long)o * D;
    const float* __restrict__ Rp = R + (long long)p * D;

    // 51 k-groups x 5 i-chunks = 255 threads; the spare thread lands in
    // chunk 5 (i in [220,264)) where bv == 0.
    const int tc = t / 51;            // i-chunk: 0..5
    const int tk = t - tc * 51;       // k-group: 0..50
    const int k0 = tk * 4;            // multiple of 4 (16B aligned)
    const int ci = tc * 44;           // multiple of 4

    // Issue per-thread R gathers early; consumed only after the compute
    // loop, so their latency hides under fill + barrier + FMAs.
    // Guarded: k0+c can reach 203 > 200 (OOB on the last R row).
    const float r0 = Rp[k0];
    const float r1 = (k0 + 1 < D) ? Rp[k0 + 1] : 0.0f;
    const float r2 = (k0 + 2 < D) ? Rp[k0 + 2] : 0.0f;
    const float r3 = (k0 + 3 < D) ? Rp[k0 + 3] : 0.0f;

    // Zero-padded fills trimmed to actual extents, one sync.
    sp[t] = (t >= PAD && t < PAD + D) ? Es[t - PAD] : 0.0f;
    {
        const int m = t + NT;
        if (m < SPLEN) sp[m] = (m < PAD + D) ? Es[m - PAD] : 0.0f;
    }
    bv[t] = (t < D) ? Eo[t] : 0.0f;
    if (t < BVLEN - NT) bv[t + NT] = 0.0f;
    __syncthreads();

    // 4 accumulators break the FMA chain; sliding-window sp loads.
    float a0 = 0.0f, a1 = 0.0f, a2 = 0.0f, a3 = 0.0f;
    float4 s0 = *reinterpret_cast<const float4*>(&sp[k0 + ci]);
    #pragma unroll
    for (int j = 0; j < 44; j += 4) {
        const float4 s1 = *reinterpret_cast<const float4*>(&sp[k0 + ci + j + 4]);
        const float4 b4 = *reinterpret_cast<const float4*>(&bv[ci + j]);

        a0 = fmaf(s0.x, b4.x, a0); a0 = fmaf(s0.y, b4.y, a0);
        a0 = fmaf(s0.z, b4.z, a0); a0 = fmaf(s0.w, b4.w, a0);

        a1 = fmaf(s0.y, b4.x, a1); a1 = fmaf(s0.z, b4.y, a1);
        a1 = fmaf(s0.w, b4.z, a1); a1 = fmaf(s1.x, b4.w, a1);

        a2 = fmaf(s0.z, b4.x, a2); a2 = fmaf(s0.w, b4.y, a2);
        a2 = fmaf(s1.x, b4.z, a2); a2 = fmaf(s1.y, b4.w, a2);

        a3 = fmaf(s0.w, b4.x, a3); a3 = fmaf(s1.x, b4.y, a3);
        a3 = fmaf(s1.y, b4.z, a3); a3 = fmaf(s1.z, b4.w, a3);

        s0 = s1;
    }

    // Fold in rv (spare chunk's accumulators are all zero).
    float v = r0 * a0;
    v = fmaf(r1, a1, v);
    v = fmaf(r2, a2, v);
    v = fmaf(r3, a3, v);

    // Warp reduce, then thread 0 sums the 8 warp partials serially
    // (2x LDS.128 + 7 adds beats a second shfl stage at 26 cyc/shfl).
    #pragma unroll
    for (int off = 16; off > 0; off >>= 1)
        v += __shfl_down_sync(0xFFFFFFFFu, v, off);
    if ((t & 31) == 0) wsum[t >> 5] = v;
    __syncthreads();

    if (t == 0) {
        const float4 w0 = *reinterpret_cast<const float4*>(&wsum[0]);
        const float4 w1 = *reinterpret_cast<const float4*>(&wsum[4]);
        out[0] = ((w0.x + w0.y) + (w0.z + w0.w))
               + ((w1.x + w1.y) + (w1.z + w1.w));
    }
}

extern "C" void kernel_launch(void* const* d_in, const int* in_sizes, int n_in,
                              void* d_out, int out_size) {
    const int*   x = (const int*)d_in[0];
    const float* E = (const float*)d_in[1];
    const float* R = (const float*)d_in[2];
    float* out = (float*)d_out;
    holo_kernel<<<1, NT>>>(x, E, R, out);
}

// round 15
// speedup vs baseline: 1.0048x; 1.0048x over previous
#include <cuda_runtime.h>

// HolographicLayer: eta = dot(R[p], ccorr_half(E[s], E[o]))
//   ccorr_half(a,b)[k] = sum_i a[k+i-100] * b[i], zero-padded, d=201
// With padded smem sp (sp[100+j] = a[j], zeros elsewhere):
//   eta = sum_k rv[k] * sum_i sp[k+i] * bv[i]
// Single block, 256 threads. Thread t owns a 4-k x 44-i register tile:
//   tc = t/51 (i-chunk), tk = t%51 (k-group of 4).
// Sliding-window sp loads (one new float4 per iteration), scalar FFMA
// with 4 independent accumulators (best-measured variant across f32x2 /
// redux / multi-block experiments). Fill phase issues ALL global loads
// into registers before any STS so the gather latencies overlap (MLP=4).

#define D      201
#define PAD    100
#define NT     256
#define SPLEN  480    // max sp index touched: 200+220+47 = 467
#define BVLEN  264    // max bv index touched: 220+43    = 263

__global__ void __launch_bounds__(NT, 1)
holo_kernel(const int* __restrict__ x,
            const float* __restrict__ E,
            const float* __restrict__ R,
            float* __restrict__ out) {
    __shared__ __align__(16) float sp[SPLEN];
    __shared__ __align__(16) float bv[BVLEN];
    __shared__ __align__(16) float wsum[NT / 32];

    const int t = threadIdx.x;

    // x is [32,3] row-major; row 0 = (s, o, p). One 16B load grabs all
    // three indices (harness buffers are 16B-aligned; x[3] is don't-care).
    const int4 xi = *reinterpret_cast<const int4*>(x);
    const int s = xi.x, o = xi.y, p = xi.z;
    const float* __restrict__ Es = E + (long long)s * D;
    const float* __restrict__ Eo = E + (long long)o * D;
    const float* __restrict__ Rp = R + (long long)p * D;

    // 51 k-groups x 5 i-chunks = 255 threads; the spare thread lands in
    // chunk 5 (i in [220,264)) where bv == 0.
    const int tc = t / 51;            // i-chunk: 0..5
    const int tk = t - tc * 51;       // k-group: 0..50
    const int k0 = tk * 4;            // multiple of 4 (16B aligned)
    const int ci = tc * 44;           // multiple of 4

    // Issue per-thread R gathers early; consumed only after the compute
    // loop, so their latency hides under fill + barrier + FMAs.
    // Guarded: k0+c can reach 203 > 200 (OOB on the last R row).
    const float r0 = Rp[k0];
    const float r1 = (k0 + 1 < D) ? Rp[k0 + 1] : 0.0f;
    const float r2 = (k0 + 2 < D) ? Rp[k0 + 2] : 0.0f;
    const float r3 = (k0 + 3 < D) ? Rp[k0 + 3] : 0.0f;

    // Fill phase: load everything into registers FIRST (4 overlapped
    // gathers), then store to smem. One sync total.
    const int m1 = t + NT;
    const float f_sp0 = (t >= PAD && t < PAD + D) ? Es[t - PAD] : 0.0f;
    const float f_sp1 = (m1 < SPLEN && m1 < PAD + D) ? Es[m1 - PAD] : 0.0f;
    const float f_bv  = (t < D) ? Eo[t] : 0.0f;

    sp[t] = f_sp0;
    if (m1 < SPLEN) sp[m1] = f_sp1;
    bv[t] = f_bv;
    if (t < BVLEN - NT) bv[t + NT] = 0.0f;
    __syncthreads();

    // 4 accumulators break the FMA chain; sliding-window sp loads.
    float a0 = 0.0f, a1 = 0.0f, a2 = 0.0f, a3 = 0.0f;
    float4 s0 = *reinterpret_cast<const float4*>(&sp[k0 + ci]);
    #pragma unroll
    for (int j = 0; j < 44; j += 4) {
        const float4 s1 = *reinterpret_cast<const float4*>(&sp[k0 + ci + j + 4]);
        const float4 b4 = *reinterpret_cast<const float4*>(&bv[ci + j]);

        a0 = fmaf(s0.x, b4.x, a0); a0 = fmaf(s0.y, b4.y, a0);
        a0 = fmaf(s0.z, b4.z, a0); a0 = fmaf(s0.w, b4.w, a0);

        a1 = fmaf(s0.y, b4.x, a1); a1 = fmaf(s0.z, b4.y, a1);
        a1 = fmaf(s0.w, b4.z, a1); a1 = fmaf(s1.x, b4.w, a1);

        a2 = fmaf(s0.z, b4.x, a2); a2 = fmaf(s0.w, b4.y, a2);
        a2 = fmaf(s1.x, b4.z, a2); a2 = fmaf(s1.y, b4.w, a2);

        a3 = fmaf(s0.w, b4.x, a3); a3 = fmaf(s1.x, b4.y, a3);
        a3 = fmaf(s1.y, b4.z, a3); a3 = fmaf(s1.z, b4.w, a3);

        s0 = s1;
    }

    // Fold in rv (spare chunk's accumulators are all zero).
    float v = r0 * a0;
    v = fmaf(r1, a1, v);
    v = fmaf(r2, a2, v);
    v = fmaf(r3, a3, v);

    // Warp reduce, then thread 0 sums the 8 warp partials serially
    // (2x LDS.128 + 7 adds beats a second shfl stage at 26 cyc/shfl).
    #pragma unroll
    for (int off = 16; off > 0; off >>= 1)
        v += __shfl_down_sync(0xFFFFFFFFu, v, off);
    if ((t & 31) == 0) wsum[t >> 5] = v;
    __syncthreads();

    if (t == 0) {
        const float4 w0 = *reinterpret_cast<const float4*>(&wsum[0]);
        const float4 w1 = *reinterpret_cast<const float4*>(&wsum[4]);
        out[0] = ((w0.x + w0.y) + (w0.z + w0.w))
               + ((w1.x + w1.y) + (w1.z + w1.w));
    }
}

extern "C" void kernel_launch(void* const* d_in, const int* in_sizes, int n_in,
                              void* d_out, int out_size) {
    const int*   x = (const int*)d_in[0];
    const float* E = (const float*)d_in[1];
    const float* R = (const float*)d_in[2];
    float* out = (float*)d_out;
    holo_kernel<<<1, NT>>>(x, E, R, out);
}